// round 10
// baseline (speedup 1.0000x reference)
#include <cuda_runtime.h>
#include <math.h>

#define TV 4352
#define NTV 278528.0f
#define EPS_BN 1e-5f

#define FMA2(d, a, b) asm("fma.rn.f32x2 %0, %1, %2, %0;" : "+l"(d) : "l"(a), "l"(b))
#define PACK2(d, s)   asm("mov.b64 %0, {%1, %1};" : "=l"(d) : "f"(s))
#define UNPK2(lo, hi, s) asm("mov.b64 {%0, %1}, %2;" : "=f"(lo), "=f"(hi) : "l"(s))
typedef unsigned long long u64;

// ---------------- device scratch ----------------
__device__ __align__(128) float g_m   [64u*384u*4352u];
__device__ __align__(128) float g_down[64u*128u*4352u];
__device__ __align__(128) float g_mout[64u*128u*4352u];
__device__ __align__(128) float g_xbar[64*64*17];
__device__ __align__(128) float g_atot[64*3*32*289];
__device__ __align__(128) float g_wt[4*64*128];      // [rt][k][row] transposed weights
__device__ float g_wq[12*64], g_wk[12*64], g_bq[12], g_bk[12];
__device__ float g_s1[8192], g_s2[8192], g_s1d[8192], g_s2d[8192];
__device__ float g_gate[8192];
__device__ float g_scale[128], g_shift[128], g_scaled[128], g_shiftd[128];

// ---- K0: transpose weights + zero down stats ----
__global__ void k_wprep(const float* __restrict__ conv_w, const float* __restrict__ down_w) {
    int id = blockIdx.x * blockDim.x + threadIdx.x;   // 32768
    if (id >= 32768) return;
    if (id < 8192) { g_s1d[id] = 0.f; g_s2d[id] = 0.f; }
    int rt = id >> 13, k = (id >> 7) & 63, row = id & 127;
    g_wt[id] = (rt < 3) ? conv_w[(rt * 128 + row) * 64 + k] : down_w[row * 64 + k];
}

// ---- K1: xbar[n][ci][v] = mean_t x0 ----
__global__ void k_xbar(const float* __restrict__ x0) {
    int b = blockIdx.x, tid = threadIdx.x;          // 4096 blocks, 128 thr
    const float* src = x0 + (size_t)b * TV;
    float acc[17];
#pragma unroll
    for (int v = 0; v < 17; v++) acc[v] = 0.f;
    for (int t = tid; t < 256; t += 128) {
        const float* p = src + t * 17;
#pragma unroll
        for (int v = 0; v < 17; v++) acc[v] += p[v];
    }
#pragma unroll
    for (int off = 16; off > 0; off >>= 1)
#pragma unroll
        for (int v = 0; v < 17; v++) acc[v] += __shfl_down_sync(~0u, acc[v], off);
    __shared__ float sm[4][17];
    if ((tid & 31) == 0)
#pragma unroll
        for (int v = 0; v < 17; v++) sm[tid >> 5][v] = acc[v];
    __syncthreads();
    if (tid < 17)
        g_xbar[b * 17 + tid] = (sm[0][tid] + sm[1][tid] + sm[2][tid] + sm[3][tid]) * (1.f / 256.f);
}

// ---- K2: pooled conv rows ----
__global__ void k_wqk(const float* __restrict__ conv_w, const float* __restrict__ conv_b) {
    int id = blockIdx.x * blockDim.x + threadIdx.x;
    if (id < 1536) {
        int which = id / 768, r = id % 768;
        int ks = r / 256, qt = (r % 256) / 64, ci = r % 64;
        int rb = ks * 128 + qt * 32 + which * 16;
        float s = 0.f;
#pragma unroll
        for (int j = 0; j < 16; j++) s += conv_w[(rb + j) * 64 + ci];
        float v = s * (1.f / 16.f);
        if (which) g_wk[(ks * 4 + qt) * 64 + ci] = v; else g_wq[(ks * 4 + qt) * 64 + ci] = v;
    }
    if (id < 24) {
        int which = id / 12, r = id % 12, ks = r / 4, qt = r % 4;
        int rb = ks * 128 + qt * 32 + which * 16;
        float s = 0.f;
#pragma unroll
        for (int j = 0; j < 16; j++) s += conv_b[rb + j];
        float v = s * (1.f / 16.f);
        if (which) g_bk[r] = v; else g_bq[r] = v;
    }
}

// ---- K3: attention -> Atot per n ----
__global__ void k_atten(const float* __restrict__ W_spa, const float* __restrict__ b_spa,
                        const float* __restrict__ W_mix, const float* __restrict__ b_mix,
                        const float* __restrict__ A_GEME, const float* __restrict__ A_SE) {
    int n = blockIdx.x, tid = threadIdx.x;          // 64 blocks, 256 thr
    __shared__ float xb[1088];
    __shared__ float Q[12][17], Kp[12][17], Qs[12][17], Ks[12][17], Km[12][17], Qm[12][17];
    for (int i = tid; i < 1088; i += 256) xb[i] = g_xbar[n * 1088 + i];
    __syncthreads();
    if (tid < 204) {
        int kq = tid / 17, v = tid % 17;
        const float* wq = g_wq + kq * 64;
        const float* wk = g_wk + kq * 64;
        float sq = 0.f, sk = 0.f;
#pragma unroll 8
        for (int ci = 0; ci < 64; ci++) {
            float xv = xb[ci * 17 + v];
            sq = fmaf(wq[ci], xv, sq); sk = fmaf(wk[ci], xv, sk);
        }
        Q[kq][v] = sq + g_bq[kq]; Kp[kq][v] = sk + g_bk[kq];
    }
    __syncthreads();
    if (tid < 204) {
        int kq = tid / 17, vp = tid % 17;
        float aq = b_spa[vp], ak = b_spa[vp], amk = b_mix[vp], amq = b_mix[vp];
#pragma unroll
        for (int v = 0; v < 17; v++) {
            float w1 = W_spa[vp * 17 + v], w2 = W_mix[vp * 17 + v];
            aq = fmaf(w1, Q[kq][v], aq); ak = fmaf(w1, Kp[kq][v], ak);
            amq = fmaf(w2, Q[kq][v], amq); amk = fmaf(w2, Kp[kq][v], amk);
        }
        Qs[kq][vp] = fmaxf(aq, 0.f); Ks[kq][vp] = fmaxf(ak, 0.f);
        Km[kq][vp] = fmaxf(amk, 0.f); Qm[kq][vp] = fmaxf(amq, 0.f);
    }
    __syncthreads();
    if (tid < 204) {
        int kq = tid / 17, ks = kq / 4, qt = kq % 4, v = tid % 17;
        float att[17], l[17];
        { // S row, weight 0.5
            float qv = Qs[kq][v], mx = -1e30f;
#pragma unroll
            for (int w = 0; w < 17; w++) { l[w] = qv * Ks[kq][w]; mx = fmaxf(mx, l[w]); }
            float s = 0.f;
#pragma unroll
            for (int w = 0; w < 17; w++) { l[w] = expf(l[w] - mx); s += l[w]; }
            float inv = 0.5f / s;
#pragma unroll
            for (int w = 0; w < 17; w++) att[w] = l[w] * inv;
        }
        if (qt >= 1) {
            float kv = Km[ks * 4 + qt - 1][v], mx = -1e30f;
#pragma unroll
            for (int w = 0; w < 17; w++) { l[w] = kv * Qm[kq][w]; mx = fmaxf(mx, l[w]); }
            float s = 0.f;
#pragma unroll
            for (int w = 0; w < 17; w++) { l[w] = expf(l[w] - mx); s += l[w]; }
            float inv = 0.25f / s;
#pragma unroll
            for (int w = 0; w < 17; w++) att[w] = fmaf(l[w], inv, att[w]);
        }
        if (qt <= 2) {
            float kv = Km[kq][v], mx = -1e30f;
#pragma unroll
            for (int w = 0; w < 17; w++) { l[w] = kv * Qm[ks * 4 + qt + 1][w]; mx = fmaxf(mx, l[w]); }
            float s = 0.f;
#pragma unroll
            for (int w = 0; w < 17; w++) { l[w] = expf(l[w] - mx); s += l[w]; }
            float inv = 0.25f / s;
#pragma unroll
            for (int w = 0; w < 17; w++) att[w] = fmaf(l[w], inv, att[w]);
        }
#pragma unroll
        for (int g = 0; g < 8; g++) {
            const float* a1 = A_SE + (ks * 8 + g) * 289 + v * 17;
            const float* a2 = A_GEME + (ks * 8 + g) * 289 + v * 17;
            float* dst = g_atot + (((size_t)n * 3 + ks) * 32 + qt * 8 + g) * 289 + v * 17;
#pragma unroll
            for (int w = 0; w < 17; w++) dst[w] = 0.5f * att[w] + a1[w] + a2[w];
        }
    }
}

// ---- K4: fused SGEMM [512,64]@[64,4352] per n — R3 geometry, A duplicated in smem ----
// A-dup: As2[k][2r]=As2[k][2r+1]=w -> one LDS.128 yields two {a,a} u64 broadcast pairs (no PACK2).
// B unchanged: natural u64 col-pairs. acc[8 rows][4 col-pairs].
__global__ void __launch_bounds__(256, 2)
k_gemm(const float* __restrict__ x0,
       const float* __restrict__ conv_b, const float* __restrict__ down_b) {
    __shared__ __align__(16) float As2[32][256];   // [k][2*row+e] duplicated  (32KB)
    __shared__ __align__(16) float Bs[32][128];    // [k][col]                 (16KB)
    int ct = blockIdx.x, rt = blockIdx.y, n = blockIdx.z, tid = threadIdx.x;
    const float* Xb = x0 + (size_t)n * 64 * TV + ct * 128;
    int bc = (tid & 31) << 2, br = tid >> 5;
    int tx = tid & 15, ty = tid >> 4;
    u64 acc[8][4];
#pragma unroll
    for (int i = 0; i < 8; i++)
#pragma unroll
        for (int j = 0; j < 4; j++) acc[i][j] = 0ull;
#pragma unroll 1
    for (int kt = 0; kt < 2; kt++) {
        if (kt) __syncthreads();
        // A slice: read transposed g_wt, store duplicated
        {
            const float* wsrc = g_wt + ((size_t)rt * 64 + kt * 32) * 128;
#pragma unroll
            for (int i = 0; i < 4; i++) {
                int f = tid + i * 256;
                int k = f >> 5, rg = f & 31;           // rg: group of 4 rows
                float4 v = *(const float4*)(wsrc + k * 128 + rg * 4);
                *(float4*)&As2[k][rg * 8]     = make_float4(v.x, v.x, v.y, v.y);
                *(float4*)&As2[k][rg * 8 + 4] = make_float4(v.z, v.z, v.w, v.w);
            }
        }
        // B slice
#pragma unroll
        for (int bb = 0; bb < 4; bb++) {
            int kr = br + bb * 8;
            *(float4*)&Bs[kr][bc] = *(const float4*)(Xb + (size_t)(kt * 32 + kr) * TV + bc);
        }
        __syncthreads();
#pragma unroll 8
        for (int k = 0; k < 32; k++) {
            const ulonglong2* ar = (const ulonglong2*)&As2[k][ty * 16];
            ulonglong2 a01 = ar[0], a23 = ar[1], a45 = ar[2], a67 = ar[3];
            const u64* brow = (const u64*)&Bs[k][tx * 8];
            u64 b0 = brow[0], b1 = brow[1], b2 = brow[2], b3 = brow[3];
            FMA2(acc[0][0], a01.x, b0); FMA2(acc[0][1], a01.x, b1);
            FMA2(acc[0][2], a01.x, b2); FMA2(acc[0][3], a01.x, b3);
            FMA2(acc[1][0], a01.y, b0); FMA2(acc[1][1], a01.y, b1);
            FMA2(acc[1][2], a01.y, b2); FMA2(acc[1][3], a01.y, b3);
            FMA2(acc[2][0], a23.x, b0); FMA2(acc[2][1], a23.x, b1);
            FMA2(acc[2][2], a23.x, b2); FMA2(acc[2][3], a23.x, b3);
            FMA2(acc[3][0], a23.y, b0); FMA2(acc[3][1], a23.y, b1);
            FMA2(acc[3][2], a23.y, b2); FMA2(acc[3][3], a23.y, b3);
            FMA2(acc[4][0], a45.x, b0); FMA2(acc[4][1], a45.x, b1);
            FMA2(acc[4][2], a45.x, b2); FMA2(acc[4][3], a45.x, b3);
            FMA2(acc[5][0], a45.y, b0); FMA2(acc[5][1], a45.y, b1);
            FMA2(acc[5][2], a45.y, b2); FMA2(acc[5][3], a45.y, b3);
            FMA2(acc[6][0], a67.x, b0); FMA2(acc[6][1], a67.x, b1);
            FMA2(acc[6][2], a67.x, b2); FMA2(acc[6][3], a67.x, b3);
            FMA2(acc[7][0], a67.y, b0); FMA2(acc[7][1], a67.y, b1);
            FMA2(acc[7][2], a67.y, b2); FMA2(acc[7][3], a67.y, b3);
        }
    }
    // unpack & store (rows = base + ty*8 + i, cols = ct*128 + tx*8 + 2j(+1))
    int colb = ct * 128 + tx * 8;
#pragma unroll
    for (int i = 0; i < 8; i++) {
        float v[8];
#pragma unroll
        for (int j = 0; j < 4; j++) UNPK2(v[2 * j], v[2 * j + 1], acc[i][j]);
        if (rt < 3) {
            int R = rt * 128 + ty * 8 + i;
            float bias = conv_b[R];
            float* dst = g_m + ((size_t)n * 384 + R) * TV + colb;
            *(float4*)dst = make_float4(v[0] + bias, v[1] + bias, v[2] + bias, v[3] + bias);
            *(float4*)(dst + 4) = make_float4(v[4] + bias, v[5] + bias, v[6] + bias, v[7] + bias);
        } else {
            int c = ty * 8 + i;
            float bias = down_b[c];
            float o[8];
#pragma unroll
            for (int j = 0; j < 8; j++) o[j] = v[j] + bias;
            float* dst = g_down + ((size_t)n * 128 + c) * TV + colb;
            *(float4*)dst = make_float4(o[0], o[1], o[2], o[3]);
            *(float4*)(dst + 4) = make_float4(o[4], o[5], o[6], o[7]);
            float s = 0.f, s2 = 0.f;
#pragma unroll
            for (int j = 0; j < 8; j++) { s += o[j]; s2 = fmaf(o[j], o[j], s2); }
#pragma unroll
            for (int off = 8; off > 0; off >>= 1) {
                s  += __shfl_down_sync(~0u, s, off);
                s2 += __shfl_down_sync(~0u, s2, off);
            }
            if (tx == 0) {
                atomicAdd(&g_s1d[n * 128 + c], s);
                atomicAdd(&g_s2d[n * 128 + c], s2);
            }
        }
    }
}

// ---- K6: graph conv + m_out moments (f32x2) ----
__global__ void __launch_bounds__(512)
k_graph() {
    int combo = blockIdx.x, n = blockIdx.y;          // (32, 64)
    int tid = threadIdx.x;
    int t = tid & 255, ch2 = tid >> 8;
    int cbase = (combo >> 3) * 32 + (combo & 7);
    int c0 = cbase + 16 * ch2;
    int c1 = c0 + 8;
    __shared__ __align__(16) float a_p[3 * 306 + 2]; // rows padded to 18 floats
    __shared__ float sred[2][512];
    for (int i = tid; i < 867; i += 512) {
        int k = i / 289, r = i % 289, v = r / 17, w = r % 17;
        a_p[k * 306 + v * 18 + w] = g_atot[(((size_t)n * 3 + k) * 32 + combo) * 289 + r];
    }
    __syncthreads();
    u64 accA[8], accB[8];
    float accA16 = 0.f, accB16 = 0.f;
#pragma unroll
    for (int p = 0; p < 8; p++) { accA[p] = 0ull; accB[p] = 0ull; }
#pragma unroll
    for (int k = 0; k < 3; k++) {
        const float* mA = g_m + ((size_t)n * 384 + k * 128 + c0) * TV + t * 17;
        const float* mB = g_m + ((size_t)n * 384 + k * 128 + c1) * TV + t * 17;
        float va[17], vb[17];
#pragma unroll
        for (int v = 0; v < 17; v++) { va[v] = mA[v]; vb[v] = mB[v]; }
#pragma unroll
        for (int v = 0; v < 17; v++) {
            const float* ar = &a_p[k * 306 + v * 18];
            u64 da, db;
            PACK2(da, va[v]); PACK2(db, vb[v]);
#pragma unroll
            for (int p = 0; p < 8; p++) {
                u64 ap = *(const u64*)(ar + 2 * p);
                FMA2(accA[p], da, ap);
                FMA2(accB[p], db, ap);
            }
            accA16 = fmaf(va[v], ar[16], accA16);
            accB16 = fmaf(vb[v], ar[16], accB16);
        }
    }
    float oA[17], oB[17];
#pragma unroll
    for (int p = 0; p < 8; p++) {
        UNPK2(oA[2 * p], oA[2 * p + 1], accA[p]);
        UNPK2(oB[2 * p], oB[2 * p + 1], accB[p]);
    }
    oA[16] = accA16; oB[16] = accB16;
    float* dA = g_mout + ((size_t)n * 128 + c0) * TV + t * 17;
    float* dB = g_mout + ((size_t)n * 128 + c1) * TV + t * 17;
    float s1a = 0.f, s2a = 0.f, s1b = 0.f, s2b = 0.f;
#pragma unroll
    for (int w = 0; w < 17; w++) {
        dA[w] = oA[w]; dB[w] = oB[w];
        s1a += oA[w]; s2a += oA[w] * oA[w];
        s1b += oB[w]; s2b += oB[w] * oB[w];
    }
#pragma unroll
    for (int cc = 0; cc < 2; cc++) {
        sred[0][tid] = cc ? s1b : s1a;
        sred[1][tid] = cc ? s2b : s2a;
        __syncthreads();
        for (int st = 128; st > 0; st >>= 1) {
            if (t < st) {
                sred[0][tid] += sred[0][tid + st];
                sred[1][tid] += sred[1][tid + st];
            }
            __syncthreads();
        }
        if (t == 0) {
            int c = cbase + 8 * (2 * ch2 + cc);
            g_s1[n * 128 + c] = sred[0][tid];
            g_s2[n * 128 + c] = sred[1][tid];
        }
        __syncthreads();
    }
}

// ---- K7: gate + BN folds ----
__global__ void __launch_bounds__(1024)
k_scalars(const float* __restrict__ charef_w,
          const float* __restrict__ bn_gamma, const float* __restrict__ bn_beta,
          const float* __restrict__ dg, const float* __restrict__ db) {
    int tid = threadIdx.x;
    float w0 = charef_w[0], w1 = charef_w[1], w2 = charef_w[2];
#pragma unroll
    for (int j = 0; j < 8; j++) {
        int idx = tid + 1024 * j;
        int c = idx & 127;
        float cr = g_s1[idx] * (1.f / NTV * 64.f);
        float crm = (c > 0) ? g_s1[idx - 1] * (1.f / NTV * 64.f) : 0.f;
        float crp = (c < 127) ? g_s1[idx + 1] * (1.f / NTV * 64.f) : 0.f;
        float conv = w0 * crm + w1 * cr + w2 * crp;
        g_gate[idx] = 1.f + 1.f / (1.f + expf(-conv));
    }
    __syncthreads();
    if (tid < 128) {
        int c = tid;
        float sm = 0.f, sm2 = 0.f, sd = 0.f, sd2 = 0.f;
        for (int n = 0; n < 64; n++) {
            int idx = n * 128 + c;
            float g = g_gate[idx];
            sm = fmaf(g, g_s1[idx], sm);
            sm2 = fmaf(g * g, g_s2[idx], sm2);
            sd += g_s1d[idx]; sd2 += g_s2d[idx];
        }
        float mean = sm / NTV;
        float var = sm2 / NTV - mean * mean;
        float sc = bn_gamma[c] * rsqrtf(var + EPS_BN);
        g_scale[c] = sc;
        g_shift[c] = bn_beta[c] - mean * sc;
        float meand = sd / NTV;
        float vard = sd2 / NTV - meand * meand;
        float scd = dg[c] * rsqrtf(vard + EPS_BN);
        g_scaled[c] = scd;
        g_shiftd[c] = db[c] - meand * scd;
    }
}

// ---- K8: epilogue ----
__global__ void k_epi(float* __restrict__ out) {
    int b = blockIdx.x, tid = threadIdx.x;
    int c = b & 127;
    float alpha = g_scale[c] * g_gate[b];
    float gam = g_scaled[c];
    float bet = g_shift[c] + g_shiftd[c];
    const float4* pm = (const float4*)(g_mout + (size_t)b * TV);
    const float4* pd = (const float4*)(g_down + (size_t)b * TV);
    float4* po = (float4*)(out + (size_t)b * TV);
    for (int i = tid; i < 1088; i += 256) {
        float4 m = pm[i], d = pd[i], o;
        o.x = fmaxf(fmaf(alpha, m.x, fmaf(gam, d.x, bet)), 0.f);
        o.y = fmaxf(fmaf(alpha, m.y, fmaf(gam, d.y, bet)), 0.f);
        o.z = fmaxf(fmaf(alpha, m.z, fmaf(gam, d.z, bet)), 0.f);
        o.w = fmaxf(fmaf(alpha, m.w, fmaf(gam, d.w, bet)), 0.f);
        po[i] = o;
    }
}

extern "C" void kernel_launch(void* const* d_in, const int* in_sizes, int n_in,
                              void* d_out, int out_size) {
    const float* x0      = (const float*)d_in[0];
    const float* conv_w  = (const float*)d_in[1];
    const float* conv_b  = (const float*)d_in[2];
    const float* W_spa   = (const float*)d_in[3];
    const float* b_spa   = (const float*)d_in[4];
    const float* W_mix   = (const float*)d_in[5];
    const float* b_mix   = (const float*)d_in[6];
    const float* A_GEME  = (const float*)d_in[7];
    const float* A_SE    = (const float*)d_in[8];
    const float* charef  = (const float*)d_in[9];
    const float* bn_g    = (const float*)d_in[10];
    const float* bn_b    = (const float*)d_in[11];
    const float* down_w  = (const float*)d_in[12];
    const float* down_b  = (const float*)d_in[13];
    const float* dbn_g   = (const float*)d_in[14];
    const float* dbn_b   = (const float*)d_in[15];
    float* out = (float*)d_out;

    k_wprep<<<128, 256>>>(conv_w, down_w);
    k_xbar<<<4096, 128>>>(x0);
    k_wqk<<<6, 256>>>(conv_w, conv_b);
    k_gemm<<<dim3(34, 4, 64), 256>>>(x0, conv_b, down_b);
    k_atten<<<64, 256>>>(W_spa, b_spa, W_mix, b_mix, A_GEME, A_SE);
    k_graph<<<dim3(32, 64), 512>>>();
    k_scalars<<<1, 1024>>>(charef, bn_g, bn_b, dbn_g, dbn_b);
    k_epi<<<8192, 256>>>(out);
}

// round 11
// speedup vs baseline: 1.2192x; 1.2192x over previous
#include <cuda_runtime.h>
#include <math.h>

#define TV 4352
#define NTV 278528.0f
#define EPS_BN 1e-5f

#define FMA2(d, a, b) asm("fma.rn.f32x2 %0, %1, %2, %0;" : "+l"(d) : "l"(a), "l"(b))
#define PACK2(d, s)   asm("mov.b64 %0, {%1, %1};" : "=l"(d) : "f"(s))
#define PACKAB(d, lo, hi) asm("mov.b64 %0, {%1, %2};" : "=l"(d) : "f"(lo), "f"(hi))
#define UNPK2(lo, hi, s) asm("mov.b64 {%0, %1}, %2;" : "=f"(lo), "=f"(hi) : "l"(s))
typedef unsigned long long u64;

// ---------------- device scratch ----------------
__device__ __align__(128) float g_m   [64u*384u*4352u];
__device__ __align__(128) float g_down[64u*128u*4352u];
__device__ __align__(128) float g_mout[64u*128u*4352u];
__device__ __align__(128) float g_xbar[64*64*17];
__device__ __align__(128) float g_atot[64*3*32*289];
__device__ __align__(128) float g_wt[4*64*128];      // [rt][k][row] transposed weights
__device__ float g_wq[12*64], g_wk[12*64], g_bq[12], g_bk[12];
__device__ float g_s1[8192], g_s2[8192], g_s1d[8192], g_s2d[8192];
__device__ float g_gate[8192];
__device__ float g_scale[128], g_shift[128], g_scaled[128], g_shiftd[128];

// ---- K1: merged prep: xbar (blocks 0..4095), wprep+zero (4096..4351), wqk (4352..4364) ----
__global__ void __launch_bounds__(128)
k_prep(const float* __restrict__ x0,
       const float* __restrict__ conv_w, const float* __restrict__ conv_b,
       const float* __restrict__ down_w) {
    int b = blockIdx.x, tid = threadIdx.x;
    if (b < 4096) {
        // xbar[n][ci][v] = mean_t x0
        const float* src = x0 + (size_t)b * TV;
        float acc[17];
#pragma unroll
        for (int v = 0; v < 17; v++) acc[v] = 0.f;
        for (int t = tid; t < 256; t += 128) {
            const float* p = src + t * 17;
#pragma unroll
            for (int v = 0; v < 17; v++) acc[v] += p[v];
        }
#pragma unroll
        for (int off = 16; off > 0; off >>= 1)
#pragma unroll
            for (int v = 0; v < 17; v++) acc[v] += __shfl_down_sync(~0u, acc[v], off);
        __shared__ float sm[4][17];
        if ((tid & 31) == 0)
#pragma unroll
            for (int v = 0; v < 17; v++) sm[tid >> 5][v] = acc[v];
        __syncthreads();
        if (tid < 17)
            g_xbar[b * 17 + tid] = (sm[0][tid] + sm[1][tid] + sm[2][tid] + sm[3][tid]) * (1.f / 256.f);
    } else if (b < 4352) {
        // weight transpose + zero down stats
        int id = (b - 4096) * 128 + tid;     // < 32768
        if (id < 8192) { g_s1d[id] = 0.f; g_s2d[id] = 0.f; }
        int rt = id >> 13, k = (id >> 7) & 63, row = id & 127;
        g_wt[id] = (rt < 3) ? conv_w[(rt * 128 + row) * 64 + k] : down_w[row * 64 + k];
    } else if (b < 4364) {
        // pooled conv rows (weights)
        int id = (b - 4352) * 128 + tid;
        if (id < 1536) {
            int which = id / 768, r = id % 768;
            int ks = r / 256, qt = (r % 256) / 64, ci = r % 64;
            int rb = ks * 128 + qt * 32 + which * 16;
            float s = 0.f;
#pragma unroll
            for (int j = 0; j < 16; j++) s += conv_w[(rb + j) * 64 + ci];
            float v = s * (1.f / 16.f);
            if (which) g_wk[(ks * 4 + qt) * 64 + ci] = v; else g_wq[(ks * 4 + qt) * 64 + ci] = v;
        }
    } else {
        // pooled conv bias
        if (tid < 24) {
            int which = tid / 12, r = tid % 12, ks = r / 4, qt = r % 4;
            int rb = ks * 128 + qt * 32 + which * 16;
            float s = 0.f;
#pragma unroll
            for (int j = 0; j < 16; j++) s += conv_b[rb + j];
            float v = s * (1.f / 16.f);
            if (which) g_bk[r] = v; else g_bq[r] = v;
        }
    }
}

// ---- K2: attention -> Atot per n ----
__global__ void k_atten(const float* __restrict__ W_spa, const float* __restrict__ b_spa,
                        const float* __restrict__ W_mix, const float* __restrict__ b_mix,
                        const float* __restrict__ A_GEME, const float* __restrict__ A_SE) {
    int n = blockIdx.x, tid = threadIdx.x;          // 64 blocks, 256 thr
    __shared__ float xb[1088];
    __shared__ float Q[12][17], Kp[12][17], Qs[12][17], Ks[12][17], Km[12][17], Qm[12][17];
    for (int i = tid; i < 1088; i += 256) xb[i] = g_xbar[n * 1088 + i];
    __syncthreads();
    if (tid < 204) {
        int kq = tid / 17, v = tid % 17;
        const float* wq = g_wq + kq * 64;
        const float* wk = g_wk + kq * 64;
        float sq = 0.f, sk = 0.f;
#pragma unroll 8
        for (int ci = 0; ci < 64; ci++) {
            float xv = xb[ci * 17 + v];
            sq = fmaf(wq[ci], xv, sq); sk = fmaf(wk[ci], xv, sk);
        }
        Q[kq][v] = sq + g_bq[kq]; Kp[kq][v] = sk + g_bk[kq];
    }
    __syncthreads();
    if (tid < 204) {
        int kq = tid / 17, vp = tid % 17;
        float aq = b_spa[vp], ak = b_spa[vp], amk = b_mix[vp], amq = b_mix[vp];
#pragma unroll
        for (int v = 0; v < 17; v++) {
            float w1 = W_spa[vp * 17 + v], w2 = W_mix[vp * 17 + v];
            aq = fmaf(w1, Q[kq][v], aq); ak = fmaf(w1, Kp[kq][v], ak);
            amq = fmaf(w2, Q[kq][v], amq); amk = fmaf(w2, Kp[kq][v], amk);
        }
        Qs[kq][vp] = fmaxf(aq, 0.f); Ks[kq][vp] = fmaxf(ak, 0.f);
        Km[kq][vp] = fmaxf(amk, 0.f); Qm[kq][vp] = fmaxf(amq, 0.f);
    }
    __syncthreads();
    if (tid < 204) {
        int kq = tid / 17, ks = kq / 4, qt = kq % 4, v = tid % 17;
        float att[17], l[17];
        { // S row, weight 0.5
            float qv = Qs[kq][v], mx = -1e30f;
#pragma unroll
            for (int w = 0; w < 17; w++) { l[w] = qv * Ks[kq][w]; mx = fmaxf(mx, l[w]); }
            float s = 0.f;
#pragma unroll
            for (int w = 0; w < 17; w++) { l[w] = expf(l[w] - mx); s += l[w]; }
            float inv = 0.5f / s;
#pragma unroll
            for (int w = 0; w < 17; w++) att[w] = l[w] * inv;
        }
        if (qt >= 1) {
            float kv = Km[ks * 4 + qt - 1][v], mx = -1e30f;
#pragma unroll
            for (int w = 0; w < 17; w++) { l[w] = kv * Qm[kq][w]; mx = fmaxf(mx, l[w]); }
            float s = 0.f;
#pragma unroll
            for (int w = 0; w < 17; w++) { l[w] = expf(l[w] - mx); s += l[w]; }
            float inv = 0.25f / s;
#pragma unroll
            for (int w = 0; w < 17; w++) att[w] = fmaf(l[w], inv, att[w]);
        }
        if (qt <= 2) {
            float kv = Km[kq][v], mx = -1e30f;
#pragma unroll
            for (int w = 0; w < 17; w++) { l[w] = kv * Qm[ks * 4 + qt + 1][w]; mx = fmaxf(mx, l[w]); }
            float s = 0.f;
#pragma unroll
            for (int w = 0; w < 17; w++) { l[w] = expf(l[w] - mx); s += l[w]; }
            float inv = 0.25f / s;
#pragma unroll
            for (int w = 0; w < 17; w++) att[w] = fmaf(l[w], inv, att[w]);
        }
#pragma unroll
        for (int g = 0; g < 8; g++) {
            const float* a1 = A_SE + (ks * 8 + g) * 289 + v * 17;
            const float* a2 = A_GEME + (ks * 8 + g) * 289 + v * 17;
            float* dst = g_atot + (((size_t)n * 3 + ks) * 32 + qt * 8 + g) * 289 + v * 17;
#pragma unroll
            for (int w = 0; w < 17; w++) dst[w] = 0.5f * att[w] + a1[w] + a2[w];
        }
    }
}

// ---- K3: fused SGEMM [512,64]@[64,4352] per n — R3 (best measured) verbatim ----
__global__ void __launch_bounds__(256, 2)
k_gemm(const float* __restrict__ x0,
       const float* __restrict__ conv_b, const float* __restrict__ down_b) {
    __shared__ __align__(16) float AsT[32][128];   // [k][row]
    __shared__ __align__(16) float Bs[32][128];    // [k][col]
    int ct = blockIdx.x, rt = blockIdx.y, n = blockIdx.z, tid = threadIdx.x;
    const float* Xb = x0 + (size_t)n * 64 * TV + ct * 128;
    int bc = (tid & 31) << 2, br = tid >> 5;
    int tx = tid & 15, ty = tid >> 4;
    u64 acc[8][4];
#pragma unroll
    for (int i = 0; i < 8; i++)
#pragma unroll
        for (int j = 0; j < 4; j++) acc[i][j] = 0ull;
#pragma unroll
    for (int kt = 0; kt < 2; kt++) {
        if (kt) __syncthreads();
        {
            const float4* wsrc = (const float4*)(g_wt + ((size_t)rt * 64 + kt * 32) * 128);
            float4* asd = (float4*)&AsT[0][0];
#pragma unroll
            for (int j = 0; j < 4; j++) asd[tid + j * 256] = wsrc[tid + j * 256];
        }
#pragma unroll
        for (int bb = 0; bb < 4; bb++) {
            int kr = br + bb * 8;
            *(float4*)&Bs[kr][bc] = *(const float4*)(Xb + (size_t)(kt * 32 + kr) * TV + bc);
        }
        __syncthreads();
#pragma unroll 8
        for (int k = 0; k < 32; k++) {
            float4 a0 = *(const float4*)&AsT[k][ty * 8];
            float4 a1 = *(const float4*)&AsT[k][ty * 8 + 4];
            const u64* brow = (const u64*)&Bs[k][tx * 8];
            u64 b0 = brow[0], b1 = brow[1], b2 = brow[2], b3 = brow[3];
            u64 pa[8];
            PACK2(pa[0], a0.x); PACK2(pa[1], a0.y); PACK2(pa[2], a0.z); PACK2(pa[3], a0.w);
            PACK2(pa[4], a1.x); PACK2(pa[5], a1.y); PACK2(pa[6], a1.z); PACK2(pa[7], a1.w);
#pragma unroll
            for (int i = 0; i < 8; i++) {
                FMA2(acc[i][0], pa[i], b0);
                FMA2(acc[i][1], pa[i], b1);
                FMA2(acc[i][2], pa[i], b2);
                FMA2(acc[i][3], pa[i], b3);
            }
        }
    }
    int colb = ct * 128 + tx * 8;
#pragma unroll
    for (int i = 0; i < 8; i++) {
        float v[8];
#pragma unroll
        for (int j = 0; j < 4; j++) UNPK2(v[2 * j], v[2 * j + 1], acc[i][j]);
        if (rt < 3) {
            int R = rt * 128 + ty * 8 + i;
            float bias = conv_b[R];
            float* dst = g_m + ((size_t)n * 384 + R) * TV + colb;
            *(float4*)dst = make_float4(v[0] + bias, v[1] + bias, v[2] + bias, v[3] + bias);
            *(float4*)(dst + 4) = make_float4(v[4] + bias, v[5] + bias, v[6] + bias, v[7] + bias);
        } else {
            int c = ty * 8 + i;
            float bias = down_b[c];
            float o[8];
#pragma unroll
            for (int j = 0; j < 8; j++) o[j] = v[j] + bias;
            float* dst = g_down + ((size_t)n * 128 + c) * TV + colb;
            *(float4*)dst = make_float4(o[0], o[1], o[2], o[3]);
            *(float4*)(dst + 4) = make_float4(o[4], o[5], o[6], o[7]);
            float s = 0.f, s2 = 0.f;
#pragma unroll
            for (int j = 0; j < 8; j++) { s += o[j]; s2 = fmaf(o[j], o[j], s2); }
#pragma unroll
            for (int off = 8; off > 0; off >>= 1) {
                s  += __shfl_down_sync(~0u, s, off);
                s2 += __shfl_down_sync(~0u, s2, off);
            }
            if (tx == 0) {
                atomicAdd(&g_s1d[n * 128 + c], s);
                atomicAdd(&g_s2d[n * 128 + c], s2);
            }
        }
    }
}

// ---- K4: graph conv + moments. Block (combo, ch2, n), 128 thr, thread = t-pair (2u,2u+1). ----
// m loads: contiguous float2 (fully coalesced). A duplicated in smem -> broadcast LDS.64 operand.
__global__ void __launch_bounds__(128)
k_graph() {
    int combo = blockIdx.x, ch2 = blockIdx.y, n = blockIdx.z;   // (32, 2, 64)
    int u = threadIdx.x;                                        // 0..127
    int cbase = (combo >> 3) * 32 + (combo & 7);
    int c0 = cbase + 16 * ch2, c1 = c0 + 8;
    __shared__ __align__(16) float ad[3 * 17 * 34];             // dup A: [k][v][2w+e]
    __shared__ float red[4][4];
    for (int i = u; i < 867; i += 128) {
        int k = i / 289, r = i % 289, v = r / 17, w = r % 17;
        float a = g_atot[(((size_t)n * 3 + k) * 32 + combo) * 289 + r];
        ad[(k * 17 + v) * 34 + 2 * w] = a;
        ad[(k * 17 + v) * 34 + 2 * w + 1] = a;
    }
    __syncthreads();
    u64 acc0[17], acc1[17];                 // pairs over channels, per t-slot
#pragma unroll
    for (int w = 0; w < 17; w++) { acc0[w] = 0ull; acc1[w] = 0ull; }
#pragma unroll
    for (int k = 0; k < 3; k++) {
        const float2* pA = (const float2*)(g_m + ((size_t)n * 384 + k * 128 + c0) * TV + u * 34);
        const float2* pB = (const float2*)(g_m + ((size_t)n * 384 + k * 128 + c1) * TV + u * 34);
        float ma[34], mb[34];
#pragma unroll
        for (int j = 0; j < 17; j++) {
            float2 xa = pA[j], xb2 = pB[j];
            ma[2 * j] = xa.x; ma[2 * j + 1] = xa.y;
            mb[2 * j] = xb2.x; mb[2 * j + 1] = xb2.y;
        }
#pragma unroll
        for (int v = 0; v < 17; v++) {
            u64 p0, p1;
            PACKAB(p0, ma[v], mb[v]);             // {m_c0_t0, m_c1_t0}
            PACKAB(p1, ma[17 + v], mb[17 + v]);   // {m_c0_t1, m_c1_t1}
            const u64* ap = (const u64*)&ad[(k * 17 + v) * 34];
#pragma unroll
            for (int w = 0; w < 17; w++) {
                u64 a2 = ap[w];
                FMA2(acc0[w], p0, a2);
                FMA2(acc1[w], p1, a2);
            }
        }
    }
    // unpack: oc0 = c0 row window [t0*17 .. t1*17+17) = 34 floats; oc1 same for c1
    float oc0[34], oc1[34];
#pragma unroll
    for (int w = 0; w < 17; w++) {
        UNPK2(oc0[w], oc1[w], acc0[w]);
        UNPK2(oc0[17 + w], oc1[17 + w], acc1[w]);
    }
    float s1a = 0.f, s2a = 0.f, s1b = 0.f, s2b = 0.f;
#pragma unroll
    for (int j = 0; j < 34; j++) {
        s1a += oc0[j]; s2a = fmaf(oc0[j], oc0[j], s2a);
        s1b += oc1[j]; s2b = fmaf(oc1[j], oc1[j], s2b);
    }
    float2* d0 = (float2*)(g_mout + ((size_t)n * 128 + c0) * TV + u * 34);
    float2* d1 = (float2*)(g_mout + ((size_t)n * 128 + c1) * TV + u * 34);
#pragma unroll
    for (int j = 0; j < 17; j++) {
        d0[j] = make_float2(oc0[2 * j], oc0[2 * j + 1]);
        d1[j] = make_float2(oc1[2 * j], oc1[2 * j + 1]);
    }
    // reduce 4 stats over 128 threads
#pragma unroll
    for (int off = 16; off > 0; off >>= 1) {
        s1a += __shfl_down_sync(~0u, s1a, off);
        s2a += __shfl_down_sync(~0u, s2a, off);
        s1b += __shfl_down_sync(~0u, s1b, off);
        s2b += __shfl_down_sync(~0u, s2b, off);
    }
    int wid = u >> 5;
    if ((u & 31) == 0) {
        red[wid][0] = s1a; red[wid][1] = s2a; red[wid][2] = s1b; red[wid][3] = s2b;
    }
    __syncthreads();
    if (u == 0) {
        float t0 = 0.f, t1 = 0.f, t2 = 0.f, t3 = 0.f;
#pragma unroll
        for (int i = 0; i < 4; i++) { t0 += red[i][0]; t1 += red[i][1]; t2 += red[i][2]; t3 += red[i][3]; }
        g_s1[n * 128 + c0] = t0; g_s2[n * 128 + c0] = t1;
        g_s1[n * 128 + c1] = t2; g_s2[n * 128 + c1] = t3;
    }
}

// ---- K5: gate + BN folds ----
__global__ void __launch_bounds__(1024)
k_scalars(const float* __restrict__ charef_w,
          const float* __restrict__ bn_gamma, const float* __restrict__ bn_beta,
          const float* __restrict__ dg, const float* __restrict__ db) {
    int tid = threadIdx.x;
    float w0 = charef_w[0], w1 = charef_w[1], w2 = charef_w[2];
#pragma unroll
    for (int j = 0; j < 8; j++) {
        int idx = tid + 1024 * j;
        int c = idx & 127;
        float cr = g_s1[idx] * (1.f / NTV * 64.f);
        float crm = (c > 0) ? g_s1[idx - 1] * (1.f / NTV * 64.f) : 0.f;
        float crp = (c < 127) ? g_s1[idx + 1] * (1.f / NTV * 64.f) : 0.f;
        float conv = w0 * crm + w1 * cr + w2 * crp;
        g_gate[idx] = 1.f + 1.f / (1.f + expf(-conv));
    }
    __syncthreads();
    if (tid < 128) {
        int c = tid;
        float sm = 0.f, sm2 = 0.f, sd = 0.f, sd2 = 0.f;
        for (int n = 0; n < 64; n++) {
            int idx = n * 128 + c;
            float g = g_gate[idx];
            sm = fmaf(g, g_s1[idx], sm);
            sm2 = fmaf(g * g, g_s2[idx], sm2);
            sd += g_s1d[idx]; sd2 += g_s2d[idx];
        }
        float mean = sm / NTV;
        float var = sm2 / NTV - mean * mean;
        float sc = bn_gamma[c] * rsqrtf(var + EPS_BN);
        g_scale[c] = sc;
        g_shift[c] = bn_beta[c] - mean * sc;
        float meand = sd / NTV;
        float vard = sd2 / NTV - meand * meand;
        float scd = dg[c] * rsqrtf(vard + EPS_BN);
        g_scaled[c] = scd;
        g_shiftd[c] = db[c] - meand * scd;
    }
}

// ---- K6: epilogue ----
__global__ void k_epi(float* __restrict__ out) {
    int b = blockIdx.x, tid = threadIdx.x;
    int c = b & 127;
    float alpha = g_scale[c] * g_gate[b];
    float gam = g_scaled[c];
    float bet = g_shift[c] + g_shiftd[c];
    const float4* pm = (const float4*)(g_mout + (size_t)b * TV);
    const float4* pd = (const float4*)(g_down + (size_t)b * TV);
    float4* po = (float4*)(out + (size_t)b * TV);
    for (int i = tid; i < 1088; i += 256) {
        float4 m = pm[i], d = pd[i], o;
        o.x = fmaxf(fmaf(alpha, m.x, fmaf(gam, d.x, bet)), 0.f);
        o.y = fmaxf(fmaf(alpha, m.y, fmaf(gam, d.y, bet)), 0.f);
        o.z = fmaxf(fmaf(alpha, m.z, fmaf(gam, d.z, bet)), 0.f);
        o.w = fmaxf(fmaf(alpha, m.w, fmaf(gam, d.w, bet)), 0.f);
        po[i] = o;
    }
}

extern "C" void kernel_launch(void* const* d_in, const int* in_sizes, int n_in,
                              void* d_out, int out_size) {
    const float* x0      = (const float*)d_in[0];
    const float* conv_w  = (const float*)d_in[1];
    const float* conv_b  = (const float*)d_in[2];
    const float* W_spa   = (const float*)d_in[3];
    const float* b_spa   = (const float*)d_in[4];
    const float* W_mix   = (const float*)d_in[5];
    const float* b_mix   = (const float*)d_in[6];
    const float* A_GEME  = (const float*)d_in[7];
    const float* A_SE    = (const float*)d_in[8];
    const float* charef  = (const float*)d_in[9];
    const float* bn_g    = (const float*)d_in[10];
    const float* bn_b    = (const float*)d_in[11];
    const float* down_w  = (const float*)d_in[12];
    const float* down_b  = (const float*)d_in[13];
    const float* dbn_g   = (const float*)d_in[14];
    const float* dbn_b   = (const float*)d_in[15];
    float* out = (float*)d_out;

    k_prep<<<4365, 128>>>(x0, conv_w, conv_b, down_w);
    k_atten<<<64, 256>>>(W_spa, b_spa, W_mix, b_mix, A_GEME, A_SE);
    k_gemm<<<dim3(34, 4, 64), 256>>>(x0, conv_b, down_b);
    k_graph<<<dim3(32, 2, 64), 128>>>();        // 4th launch -> profiled
    k_scalars<<<1, 1024>>>(charef, bn_g, bn_b, dbn_g, dbn_b);
    k_epi<<<8192, 256>>>(out);
}

// round 12
// speedup vs baseline: 1.2379x; 1.0154x over previous
#include <cuda_runtime.h>
#include <math.h>

#define TV 4352
#define NTV 278528.0f
#define EPS_BN 1e-5f

#define FMA2(d, a, b) asm("fma.rn.f32x2 %0, %1, %2, %0;" : "+l"(d) : "l"(a), "l"(b))
#define PACK2(d, s)   asm("mov.b64 %0, {%1, %1};" : "=l"(d) : "f"(s))
#define PACKAB(d, lo, hi) asm("mov.b64 %0, {%1, %2};" : "=l"(d) : "f"(lo), "f"(hi))
#define UNPK2(lo, hi, s) asm("mov.b64 {%0, %1}, %2;" : "=f"(lo), "=f"(hi) : "l"(s))
typedef unsigned long long u64;

// ---------------- device scratch ----------------
__device__ __align__(128) float g_m   [64u*384u*4352u];
__device__ __align__(128) float g_down[64u*128u*4352u];
__device__ __align__(128) float g_mout[64u*128u*4352u];
__device__ __align__(128) float g_xbar[64*64*17];
__device__ __align__(128) float g_atot[64*3*32*289];
__device__ __align__(128) float g_wt[4*64*128];      // [rt][k][row] transposed weights
__device__ float g_wq[12*64], g_wk[12*64], g_bq[12], g_bk[12];
__device__ float g_s1[8192], g_s2[8192], g_s1d[8192], g_s2d[8192];
__device__ float g_gate[8192];
__device__ float g_scale[128], g_shift[128], g_scaled[128], g_shiftd[128];

// ---- K1: merged prep: xbar (blocks 0..4095), wprep+zero (4096..4351), wqk (4352..4364) ----
__global__ void __launch_bounds__(128)
k_prep(const float* __restrict__ x0,
       const float* __restrict__ conv_w, const float* __restrict__ conv_b,
       const float* __restrict__ down_w) {
    int b = blockIdx.x, tid = threadIdx.x;
    if (b < 4096) {
        const float* src = x0 + (size_t)b * TV;
        float acc[17];
#pragma unroll
        for (int v = 0; v < 17; v++) acc[v] = 0.f;
        for (int t = tid; t < 256; t += 128) {
            const float* p = src + t * 17;
#pragma unroll
            for (int v = 0; v < 17; v++) acc[v] += p[v];
        }
#pragma unroll
        for (int off = 16; off > 0; off >>= 1)
#pragma unroll
            for (int v = 0; v < 17; v++) acc[v] += __shfl_down_sync(~0u, acc[v], off);
        __shared__ float sm[4][17];
        if ((tid & 31) == 0)
#pragma unroll
            for (int v = 0; v < 17; v++) sm[tid >> 5][v] = acc[v];
        __syncthreads();
        if (tid < 17)
            g_xbar[b * 17 + tid] = (sm[0][tid] + sm[1][tid] + sm[2][tid] + sm[3][tid]) * (1.f / 256.f);
    } else if (b < 4352) {
        int id = (b - 4096) * 128 + tid;     // < 32768
        if (id < 8192) { g_s1d[id] = 0.f; g_s2d[id] = 0.f; }
        int rt = id >> 13, k = (id >> 7) & 63, row = id & 127;
        g_wt[id] = (rt < 3) ? conv_w[(rt * 128 + row) * 64 + k] : down_w[row * 64 + k];
    } else if (b < 4364) {
        int id = (b - 4352) * 128 + tid;
        if (id < 1536) {
            int which = id / 768, r = id % 768;
            int ks = r / 256, qt = (r % 256) / 64, ci = r % 64;
            int rb = ks * 128 + qt * 32 + which * 16;
            float s = 0.f;
#pragma unroll
            for (int j = 0; j < 16; j++) s += conv_w[(rb + j) * 64 + ci];
            float v = s * (1.f / 16.f);
            if (which) g_wk[(ks * 4 + qt) * 64 + ci] = v; else g_wq[(ks * 4 + qt) * 64 + ci] = v;
        }
    } else {
        if (tid < 24) {
            int which = tid / 12, r = tid % 12, ks = r / 4, qt = r % 4;
            int rb = ks * 128 + qt * 32 + which * 16;
            float s = 0.f;
#pragma unroll
            for (int j = 0; j < 16; j++) s += conv_b[rb + j];
            float v = s * (1.f / 16.f);
            if (which) g_bk[r] = v; else g_bq[r] = v;
        }
    }
}

// ---- K2: attention -> Atot per n ----
__global__ void k_atten(const float* __restrict__ W_spa, const float* __restrict__ b_spa,
                        const float* __restrict__ W_mix, const float* __restrict__ b_mix,
                        const float* __restrict__ A_GEME, const float* __restrict__ A_SE) {
    int n = blockIdx.x, tid = threadIdx.x;          // 64 blocks, 256 thr
    __shared__ float xb[1088];
    __shared__ float Q[12][17], Kp[12][17], Qs[12][17], Ks[12][17], Km[12][17], Qm[12][17];
    for (int i = tid; i < 1088; i += 256) xb[i] = g_xbar[n * 1088 + i];
    __syncthreads();
    if (tid < 204) {
        int kq = tid / 17, v = tid % 17;
        const float* wq = g_wq + kq * 64;
        const float* wk = g_wk + kq * 64;
        float sq = 0.f, sk = 0.f;
#pragma unroll 8
        for (int ci = 0; ci < 64; ci++) {
            float xv = xb[ci * 17 + v];
            sq = fmaf(wq[ci], xv, sq); sk = fmaf(wk[ci], xv, sk);
        }
        Q[kq][v] = sq + g_bq[kq]; Kp[kq][v] = sk + g_bk[kq];
    }
    __syncthreads();
    if (tid < 204) {
        int kq = tid / 17, vp = tid % 17;
        float aq = b_spa[vp], ak = b_spa[vp], amk = b_mix[vp], amq = b_mix[vp];
#pragma unroll
        for (int v = 0; v < 17; v++) {
            float w1 = W_spa[vp * 17 + v], w2 = W_mix[vp * 17 + v];
            aq = fmaf(w1, Q[kq][v], aq); ak = fmaf(w1, Kp[kq][v], ak);
            amq = fmaf(w2, Q[kq][v], amq); amk = fmaf(w2, Kp[kq][v], amk);
        }
        Qs[kq][vp] = fmaxf(aq, 0.f); Ks[kq][vp] = fmaxf(ak, 0.f);
        Km[kq][vp] = fmaxf(amk, 0.f); Qm[kq][vp] = fmaxf(amq, 0.f);
    }
    __syncthreads();
    if (tid < 204) {
        int kq = tid / 17, ks = kq / 4, qt = kq % 4, v = tid % 17;
        float att[17], l[17];
        { // S row, weight 0.5
            float qv = Qs[kq][v], mx = -1e30f;
#pragma unroll
            for (int w = 0; w < 17; w++) { l[w] = qv * Ks[kq][w]; mx = fmaxf(mx, l[w]); }
            float s = 0.f;
#pragma unroll
            for (int w = 0; w < 17; w++) { l[w] = expf(l[w] - mx); s += l[w]; }
            float inv = 0.5f / s;
#pragma unroll
            for (int w = 0; w < 17; w++) att[w] = l[w] * inv;
        }
        if (qt >= 1) {
            float kv = Km[ks * 4 + qt - 1][v], mx = -1e30f;
#pragma unroll
            for (int w = 0; w < 17; w++) { l[w] = kv * Qm[kq][w]; mx = fmaxf(mx, l[w]); }
            float s = 0.f;
#pragma unroll
            for (int w = 0; w < 17; w++) { l[w] = expf(l[w] - mx); s += l[w]; }
            float inv = 0.25f / s;
#pragma unroll
            for (int w = 0; w < 17; w++) att[w] = fmaf(l[w], inv, att[w]);
        }
        if (qt <= 2) {
            float kv = Km[kq][v], mx = -1e30f;
#pragma unroll
            for (int w = 0; w < 17; w++) { l[w] = kv * Qm[ks * 4 + qt + 1][w]; mx = fmaxf(mx, l[w]); }
            float s = 0.f;
#pragma unroll
            for (int w = 0; w < 17; w++) { l[w] = expf(l[w] - mx); s += l[w]; }
            float inv = 0.25f / s;
#pragma unroll
            for (int w = 0; w < 17; w++) att[w] = fmaf(l[w], inv, att[w]);
        }
#pragma unroll
        for (int g = 0; g < 8; g++) {
            const float* a1 = A_SE + (ks * 8 + g) * 289 + v * 17;
            const float* a2 = A_GEME + (ks * 8 + g) * 289 + v * 17;
            float* dst = g_atot + (((size_t)n * 3 + ks) * 32 + qt * 8 + g) * 289 + v * 17;
#pragma unroll
            for (int w = 0; w < 17; w++) dst[w] = 0.5f * att[w] + a1[w] + a2[w];
        }
    }
}

// ---- K3: fused SGEMM [512,64]@[64,4352] per n — R3 (best measured) verbatim ----
__global__ void __launch_bounds__(256, 2)
k_gemm(const float* __restrict__ x0,
       const float* __restrict__ conv_b, const float* __restrict__ down_b) {
    __shared__ __align__(16) float AsT[32][128];   // [k][row]
    __shared__ __align__(16) float Bs[32][128];    // [k][col]
    int ct = blockIdx.x, rt = blockIdx.y, n = blockIdx.z, tid = threadIdx.x;
    const float* Xb = x0 + (size_t)n * 64 * TV + ct * 128;
    int bc = (tid & 31) << 2, br = tid >> 5;
    int tx = tid & 15, ty = tid >> 4;
    u64 acc[8][4];
#pragma unroll
    for (int i = 0; i < 8; i++)
#pragma unroll
        for (int j = 0; j < 4; j++) acc[i][j] = 0ull;
#pragma unroll
    for (int kt = 0; kt < 2; kt++) {
        if (kt) __syncthreads();
        {
            const float4* wsrc = (const float4*)(g_wt + ((size_t)rt * 64 + kt * 32) * 128);
            float4* asd = (float4*)&AsT[0][0];
#pragma unroll
            for (int j = 0; j < 4; j++) asd[tid + j * 256] = wsrc[tid + j * 256];
        }
#pragma unroll
        for (int bb = 0; bb < 4; bb++) {
            int kr = br + bb * 8;
            *(float4*)&Bs[kr][bc] = *(const float4*)(Xb + (size_t)(kt * 32 + kr) * TV + bc);
        }
        __syncthreads();
#pragma unroll 8
        for (int k = 0; k < 32; k++) {
            float4 a0 = *(const float4*)&AsT[k][ty * 8];
            float4 a1 = *(const float4*)&AsT[k][ty * 8 + 4];
            const u64* brow = (const u64*)&Bs[k][tx * 8];
            u64 b0 = brow[0], b1 = brow[1], b2 = brow[2], b3 = brow[3];
            u64 pa[8];
            PACK2(pa[0], a0.x); PACK2(pa[1], a0.y); PACK2(pa[2], a0.z); PACK2(pa[3], a0.w);
            PACK2(pa[4], a1.x); PACK2(pa[5], a1.y); PACK2(pa[6], a1.z); PACK2(pa[7], a1.w);
#pragma unroll
            for (int i = 0; i < 8; i++) {
                FMA2(acc[i][0], pa[i], b0);
                FMA2(acc[i][1], pa[i], b1);
                FMA2(acc[i][2], pa[i], b2);
                FMA2(acc[i][3], pa[i], b3);
            }
        }
    }
    int colb = ct * 128 + tx * 8;
#pragma unroll
    for (int i = 0; i < 8; i++) {
        float v[8];
#pragma unroll
        for (int j = 0; j < 4; j++) UNPK2(v[2 * j], v[2 * j + 1], acc[i][j]);
        if (rt < 3) {
            int R = rt * 128 + ty * 8 + i;
            float bias = conv_b[R];
            float* dst = g_m + ((size_t)n * 384 + R) * TV + colb;
            *(float4*)dst = make_float4(v[0] + bias, v[1] + bias, v[2] + bias, v[3] + bias);
            *(float4*)(dst + 4) = make_float4(v[4] + bias, v[5] + bias, v[6] + bias, v[7] + bias);
        } else {
            int c = ty * 8 + i;
            float bias = down_b[c];
            float o[8];
#pragma unroll
            for (int j = 0; j < 8; j++) o[j] = v[j] + bias;
            float* dst = g_down + ((size_t)n * 128 + c) * TV + colb;
            *(float4*)dst = make_float4(o[0], o[1], o[2], o[3]);
            *(float4*)(dst + 4) = make_float4(o[4], o[5], o[6], o[7]);
            float s = 0.f, s2 = 0.f;
#pragma unroll
            for (int j = 0; j < 8; j++) { s += o[j]; s2 = fmaf(o[j], o[j], s2); }
#pragma unroll
            for (int off = 8; off > 0; off >>= 1) {
                s  += __shfl_down_sync(~0u, s, off);
                s2 += __shfl_down_sync(~0u, s2, off);
            }
            if (tx == 0) {
                atomicAdd(&g_s1d[n * 128 + c], s);
                atomicAdd(&g_s2d[n * 128 + c], s2);
            }
        }
    }
}

// ---- K4: graph conv + moments. Block (combo, ch2, n), 256 thr. ----
// Thread = (t-pair u, channel-selector cs): ONE channel, pair over t-slots.
// acc 17 u64 + m 34 floats -> ~80 regs -> 3 blocks/SM (24 warps).
__global__ void __launch_bounds__(256, 3)
k_graph() {
    int combo = blockIdx.x, ch2 = blockIdx.y, n = blockIdx.z;   // (32, 2, 64)
    int tid = threadIdx.x;
    int u = tid & 127, cs = tid >> 7;                            // t-pair, channel sel
    int cbase = (combo >> 3) * 32 + (combo & 7);
    int c = cbase + 16 * ch2 + 8 * cs;
    __shared__ __align__(16) float ad[3 * 17 * 34];              // dup A: [k][v][2w+e]
    __shared__ float red[8][2];
    for (int i = tid; i < 867; i += 256) {
        int k = i / 289, r = i % 289, v = r / 17, w = r % 17;
        float a = g_atot[(((size_t)n * 3 + k) * 32 + combo) * 289 + r];
        ad[(k * 17 + v) * 34 + 2 * w] = a;
        ad[(k * 17 + v) * 34 + 2 * w + 1] = a;
    }
    __syncthreads();
    u64 acc[17];                      // pairs over (t0, t1)
#pragma unroll
    for (int w = 0; w < 17; w++) acc[w] = 0ull;
#pragma unroll
    for (int k = 0; k < 3; k++) {
        const float2* pm = (const float2*)(g_m + ((size_t)n * 384 + k * 128 + c) * TV + u * 34);
        float m[34];
#pragma unroll
        for (int j = 0; j < 17; j++) {
            float2 x = pm[j];
            m[2 * j] = x.x; m[2 * j + 1] = x.y;
        }
#pragma unroll
        for (int v = 0; v < 17; v++) {
            u64 p;
            PACKAB(p, m[v], m[17 + v]);        // {m[t0,v], m[t1,v]}
            const u64* ap = (const u64*)&ad[(k * 17 + v) * 34];
#pragma unroll
            for (int w = 0; w < 17; w++)
                FMA2(acc[w], p, ap[w]);
        }
    }
    float ov[34];
#pragma unroll
    for (int w = 0; w < 17; w++)
        UNPK2(ov[w], ov[17 + w], acc[w]);
    float s1 = 0.f, s2 = 0.f;
#pragma unroll
    for (int j = 0; j < 34; j++) { s1 += ov[j]; s2 = fmaf(ov[j], ov[j], s2); }
    float2* d = (float2*)(g_mout + ((size_t)n * 128 + c) * TV + u * 34);
#pragma unroll
    for (int j = 0; j < 17; j++)
        d[j] = make_float2(ov[2 * j], ov[2 * j + 1]);
    // reduce stats over the 128 threads of this channel (4 warps each half)
#pragma unroll
    for (int off = 16; off > 0; off >>= 1) {
        s1 += __shfl_down_sync(~0u, s1, off);
        s2 += __shfl_down_sync(~0u, s2, off);
    }
    int wid = tid >> 5;
    if ((tid & 31) == 0) { red[wid][0] = s1; red[wid][1] = s2; }
    __syncthreads();
    if ((tid & 127) == 0) {
        int wb = cs * 4;
        float t1 = red[wb][0] + red[wb + 1][0] + red[wb + 2][0] + red[wb + 3][0];
        float t2 = red[wb][1] + red[wb + 1][1] + red[wb + 2][1] + red[wb + 3][1];
        g_s1[n * 128 + c] = t1;
        g_s2[n * 128 + c] = t2;
    }
}

// ---- K5: gate + BN folds ----
__global__ void __launch_bounds__(1024)
k_scalars(const float* __restrict__ charef_w,
          const float* __restrict__ bn_gamma, const float* __restrict__ bn_beta,
          const float* __restrict__ dg, const float* __restrict__ db) {
    int tid = threadIdx.x;
    float w0 = charef_w[0], w1 = charef_w[1], w2 = charef_w[2];
#pragma unroll
    for (int j = 0; j < 8; j++) {
        int idx = tid + 1024 * j;
        int c = idx & 127;
        float cr = g_s1[idx] * (1.f / NTV * 64.f);
        float crm = (c > 0) ? g_s1[idx - 1] * (1.f / NTV * 64.f) : 0.f;
        float crp = (c < 127) ? g_s1[idx + 1] * (1.f / NTV * 64.f) : 0.f;
        float conv = w0 * crm + w1 * cr + w2 * crp;
        g_gate[idx] = 1.f + 1.f / (1.f + expf(-conv));
    }
    __syncthreads();
    if (tid < 128) {
        int c = tid;
        float sm = 0.f, sm2 = 0.f, sd = 0.f, sd2 = 0.f;
        for (int n = 0; n < 64; n++) {
            int idx = n * 128 + c;
            float g = g_gate[idx];
            sm = fmaf(g, g_s1[idx], sm);
            sm2 = fmaf(g * g, g_s2[idx], sm2);
            sd += g_s1d[idx]; sd2 += g_s2d[idx];
        }
        float mean = sm / NTV;
        float var = sm2 / NTV - mean * mean;
        float sc = bn_gamma[c] * rsqrtf(var + EPS_BN);
        g_scale[c] = sc;
        g_shift[c] = bn_beta[c] - mean * sc;
        float meand = sd / NTV;
        float vard = sd2 / NTV - meand * meand;
        float scd = dg[c] * rsqrtf(vard + EPS_BN);
        g_scaled[c] = scd;
        g_shiftd[c] = db[c] - meand * scd;
    }
}

// ---- K6: epilogue ----
__global__ void k_epi(float* __restrict__ out) {
    int b = blockIdx.x, tid = threadIdx.x;
    int c = b & 127;
    float alpha = g_scale[c] * g_gate[b];
    float gam = g_scaled[c];
    float bet = g_shift[c] + g_shiftd[c];
    const float4* pm = (const float4*)(g_mout + (size_t)b * TV);
    const float4* pd = (const float4*)(g_down + (size_t)b * TV);
    float4* po = (float4*)(out + (size_t)b * TV);
    for (int i = tid; i < 1088; i += 256) {
        float4 m = pm[i], d = pd[i], o;
        o.x = fmaxf(fmaf(alpha, m.x, fmaf(gam, d.x, bet)), 0.f);
        o.y = fmaxf(fmaf(alpha, m.y, fmaf(gam, d.y, bet)), 0.f);
        o.z = fmaxf(fmaf(alpha, m.z, fmaf(gam, d.z, bet)), 0.f);
        o.w = fmaxf(fmaf(alpha, m.w, fmaf(gam, d.w, bet)), 0.f);
        po[i] = o;
    }
}

extern "C" void kernel_launch(void* const* d_in, const int* in_sizes, int n_in,
                              void* d_out, int out_size) {
    const float* x0      = (const float*)d_in[0];
    const float* conv_w  = (const float*)d_in[1];
    const float* conv_b  = (const float*)d_in[2];
    const float* W_spa   = (const float*)d_in[3];
    const float* b_spa   = (const float*)d_in[4];
    const float* W_mix   = (const float*)d_in[5];
    const float* b_mix   = (const float*)d_in[6];
    const float* A_GEME  = (const float*)d_in[7];
    const float* A_SE    = (const float*)d_in[8];
    const float* charef  = (const float*)d_in[9];
    const float* bn_g    = (const float*)d_in[10];
    const float* bn_b    = (const float*)d_in[11];
    const float* down_w  = (const float*)d_in[12];
    const float* down_b  = (const float*)d_in[13];
    const float* dbn_g   = (const float*)d_in[14];
    const float* dbn_b   = (const float*)d_in[15];
    float* out = (float*)d_out;

    k_prep<<<4365, 128>>>(x0, conv_w, conv_b, down_w);
    k_atten<<<64, 256>>>(W_spa, b_spa, W_mix, b_mix, A_GEME, A_SE);
    k_gemm<<<dim3(34, 4, 64), 256>>>(x0, conv_b, down_b);
    k_graph<<<dim3(32, 2, 64), 256>>>();        // 4th launch -> profiled
    k_scalars<<<1, 1024>>>(charef, bn_g, bn_b, dbn_g, dbn_b);
    k_epi<<<8192, 256>>>(out);
}